// round 6
// baseline (speedup 1.0000x reference)
#include <cuda_runtime.h>
#include <math.h>

// Problem shape (fixed): encoder_output [C,K,H] fp32, W [H,H] fp32.
#define C_DIM 512
#define K_DIM 64
#define H_DIM 1024
#define H4 (H_DIM / 4)

// GEMM: M=512, N=1024, K=1024. CTA 64x128, BK=16, 8 warps (32x32), split-K=4.
#define SPLITK 4
#define KSEG (H_DIM / SPLITK)   // 256
#define NITER (KSEG / 16)       // 16
#define STAGES 3

// smem geometry (floats)
#define A_STRIDE 36             // 16 hi + 16 lo + 4 pad
#define A_STAGE (64 * A_STRIDE)       // 2304
#define B_STAGE 4608                   // max(128*36, 2*16*136)
#define SMEM_FLOATS (STAGES * (A_STAGE + B_STAGE))   // 20736 -> 82944 B

// -------------------------------------------------------------------------
// Scratch (device globals only)
// -------------------------------------------------------------------------
__device__ __align__(16) float g_s   [C_DIM * H_DIM];
__device__ __align__(16) float g_shi [C_DIM * H_DIM];
__device__ __align__(16) float g_slo [C_DIM * H_DIM];
__device__ __align__(16) float g_c   [C_DIM * H_DIM];
__device__ __align__(16) float g_chi [C_DIM * H_DIM];
__device__ __align__(16) float g_clo [C_DIM * H_DIM];
__device__ __align__(16) float g_whi [H_DIM * H_DIM];
__device__ __align__(16) float g_wlo [H_DIM * H_DIM];
__device__ __align__(16) float g_part[SPLITK][C_DIM * H_DIM];
__device__ __align__(16) float g_b   [C_DIM * K_DIM];

// -------------------------------------------------------------------------
// PTX helpers
// -------------------------------------------------------------------------
__device__ __forceinline__ float tf32_hi(float x) {
    unsigned r;
    asm("cvt.rna.tf32.f32 %0, %1;" : "=r"(r) : "f"(x));
    return __uint_as_float(r);
}
__device__ __forceinline__ void split2(float x, float& hi, float& lo) {
    hi = tf32_hi(x);
    lo = tf32_hi(x - hi);
}

__device__ __forceinline__ void mma_tf32(float c[4],
                                         float a0, float a1, float a2, float a3,
                                         float b0, float b1) {
    asm volatile(
        "mma.sync.aligned.m16n8k8.row.col.f32.tf32.tf32.f32 "
        "{%0,%1,%2,%3}, {%4,%5,%6,%7}, {%8,%9}, {%0,%1,%2,%3};"
        : "+f"(c[0]), "+f"(c[1]), "+f"(c[2]), "+f"(c[3])
        : "r"(__float_as_uint(a0)), "r"(__float_as_uint(a1)),
          "r"(__float_as_uint(a2)), "r"(__float_as_uint(a3)),
          "r"(__float_as_uint(b0)), "r"(__float_as_uint(b1)));
}

__device__ __forceinline__ void cp16(void* smem, const void* gmem) {
    unsigned s = (unsigned)__cvta_generic_to_shared(smem);
    asm volatile("cp.async.cg.shared.global [%0], [%1], 16;" :: "r"(s), "l"(gmem));
}
__device__ __forceinline__ void cp_commit() { asm volatile("cp.async.commit_group;"); }
__device__ __forceinline__ void cp_wait1()  { asm volatile("cp.async.wait_group 1;" ::: "memory"); }

// -------------------------------------------------------------------------
// Split W into tf32 hi/lo planes (runs once per launch).
// grid 1024, block 256: one row of W per CTA, float4 per thread.
// -------------------------------------------------------------------------
__global__ __launch_bounds__(256) void split_w_kernel(const float* __restrict__ W) {
    const int r = blockIdx.x, t = threadIdx.x;
    float4 v = reinterpret_cast<const float4*>(W)[r * H4 + t];
    float4 h, l;
    split2(v.x, h.x, l.x); split2(v.y, h.y, l.y);
    split2(v.z, h.z, l.z); split2(v.w, h.w, l.w);
    reinterpret_cast<float4*>(g_whi)[r * H4 + t] = h;
    reinterpret_cast<float4*>(g_wlo)[r * H4 + t] = l;
}

// -------------------------------------------------------------------------
// Kernel 1: iteration-1 weighted sum (uniform d=1/64); writes s + hi/lo; b<-0.
// -------------------------------------------------------------------------
__global__ __launch_bounds__(256) void ws_uniform_kernel(const float* __restrict__ x) {
    const int c = blockIdx.x;
    const int t = threadIdx.x;
    const float4* xp = reinterpret_cast<const float4*>(x) + (size_t)c * K_DIM * H4;

    float4 acc = make_float4(0.f, 0.f, 0.f, 0.f);
#pragma unroll 8
    for (int k = 0; k < K_DIM; ++k) {
        float4 v = __ldg(&xp[k * H4 + t]);
        acc.x += v.x; acc.y += v.y; acc.z += v.z; acc.w += v.w;
    }
    const float inv = 1.0f / (float)K_DIM;
    float4 o = make_float4(acc.x * inv, acc.y * inv, acc.z * inv, acc.w * inv);
    reinterpret_cast<float4*>(g_s)[c * H4 + t] = o;

    float4 h, l;
    split2(o.x, h.x, l.x); split2(o.y, h.y, l.y);
    split2(o.z, h.z, l.z); split2(o.w, h.w, l.w);
    reinterpret_cast<float4*>(g_shi)[c * H4 + t] = h;
    reinterpret_cast<float4*>(g_slo)[c * H4 + t] = l;

    if (t < K_DIM) g_b[c * K_DIM + t] = 0.0f;
}

// -------------------------------------------------------------------------
// Tensor-core 3xTF32 GEMM on PRE-SPLIT operands.
//   out[m,n] = sum_k A[m,k]*(BT ? B[n,k] : B[k,n]) ;  A = Ahi+Alo, B = Bhi+Blo
// CTA 64x128, BK=16, 256 thr (8 warps, 2x4, warp 32x32), 3-stage cp.async.
// smem A rows: [hi(16) | lo(16) | pad(4)] stride 36.
// smem B (BT=1): same row layout, 128 rows.  (BT=0): hi plane [16][136] + lo plane.
// -------------------------------------------------------------------------
template <int BT>
__global__ __launch_bounds__(256, 2) void gemm_tc_kernel(const float* __restrict__ Ahi,
                                                         const float* __restrict__ Alo,
                                                         const float* __restrict__ Bhi,
                                                         const float* __restrict__ Blo,
                                                         float* __restrict__ part_base) {
    extern __shared__ __align__(16) float smem[];
    float* sA = smem;                       // STAGES * A_STAGE
    float* sB = smem + STAGES * A_STAGE;    // STAGES * B_STAGE

    const int tid  = threadIdx.x;
    const int w    = tid >> 5, lane = tid & 31;
    const int g    = lane >> 2, tig = lane & 3;
    const int wm   = w >> 2;          // 0..1
    const int wn   = w & 3;           // 0..3
    const int m0   = blockIdx.y * 64;
    const int n0   = blockIdx.x * 128;
    const int kbeg = blockIdx.z * KSEG;

    float acc[2][4][4];
#pragma unroll
    for (int i = 0; i < 2; ++i)
#pragma unroll
        for (int j = 0; j < 4; ++j)
#pragma unroll
            for (int q = 0; q < 4; ++q) acc[i][j][q] = 0.f;

    auto issue = [&](int it, int buf) {
        const int kw = kbeg + it * 16;
        float* aS = sA + buf * A_STAGE;
        float* bS = sB + buf * B_STAGE;
        {   // A: 64 rows, hi->cols 0..15, lo->cols 16..31
            const int q = tid & 3, row = tid >> 2;
            const size_t go = (size_t)(m0 + row) * H_DIM + kw + q * 4;
            cp16(&aS[row * A_STRIDE + q * 4],      Ahi + go);
            cp16(&aS[row * A_STRIDE + 16 + q * 4], Alo + go);
        }
        if (BT) {   // B[n,k]: 128 rows, same packing, stride 36
            const int q = tid & 3, r0 = tid >> 2;
#pragma unroll
            for (int rr = 0; rr < 2; ++rr) {
                const int row = r0 + rr * 64;
                const size_t go = (size_t)(n0 + row) * H_DIM + kw + q * 4;
                cp16(&bS[row * A_STRIDE + q * 4],      Bhi + go);
                cp16(&bS[row * A_STRIDE + 16 + q * 4], Blo + go);
            }
        } else {    // B[k,n]: hi plane [16][136], lo plane at +16*136
            const int f = tid & 31, r0 = tid >> 5;
#pragma unroll
            for (int rr = 0; rr < 2; ++rr) {
                const int row = r0 + rr * 8;
                const size_t go = (size_t)(kw + row) * H_DIM + n0 + f * 4;
                cp16(&bS[row * 136 + f * 4],            Bhi + go);
                cp16(&bS[16 * 136 + row * 136 + f * 4], Blo + go);
            }
        }
        cp_commit();
    };

    issue(0, 0);
    issue(1, 1);
    for (int it = 0; it < NITER; ++it) {
        const int buf = it % STAGES;
        cp_wait1();
        __syncthreads();
        if (it + 2 < NITER) issue(it + 2, (it + 2) % STAGES);

        const float* aS = sA + buf * A_STAGE;
        const float* bS = sB + buf * B_STAGE;
#pragma unroll
        for (int ks = 0; ks < 16; ks += 8) {
            float ahi[2][4], alo[2][4];
#pragma unroll
            for (int i = 0; i < 2; ++i) {
                const int m = wm * 32 + i * 16;
                const float* r0 = &aS[(m + g)     * A_STRIDE + ks + tig];
                const float* r1 = &aS[(m + g + 8) * A_STRIDE + ks + tig];
                ahi[i][0] = r0[0];  ahi[i][1] = r1[0];
                ahi[i][2] = r0[4];  ahi[i][3] = r1[4];
                alo[i][0] = r0[16]; alo[i][1] = r1[16];
                alo[i][2] = r0[20]; alo[i][3] = r1[20];
            }
#pragma unroll
            for (int j = 0; j < 4; ++j) {
                const int n = wn * 32 + j * 8;
                float bh0, bh1, bl0, bl1;
                if (BT) {
                    const float* r = &bS[(n + g) * A_STRIDE + ks + tig];
                    bh0 = r[0]; bh1 = r[4]; bl0 = r[16]; bl1 = r[20];
                } else {
                    bh0 = bS[(ks + tig)     * 136 + n + g];
                    bh1 = bS[(ks + tig + 4) * 136 + n + g];
                    bl0 = bS[16 * 136 + (ks + tig)     * 136 + n + g];
                    bl1 = bS[16 * 136 + (ks + tig + 4) * 136 + n + g];
                }
#pragma unroll
                for (int i = 0; i < 2; ++i) {
                    mma_tf32(acc[i][j], ahi[i][0], ahi[i][1], ahi[i][2], ahi[i][3], bh0, bh1);
                    mma_tf32(acc[i][j], ahi[i][0], ahi[i][1], ahi[i][2], ahi[i][3], bl0, bl1);
                    mma_tf32(acc[i][j], alo[i][0], alo[i][1], alo[i][2], alo[i][3], bh0, bh1);
                }
            }
        }
    }

    float* P = part_base + (size_t)blockIdx.z * (C_DIM * H_DIM);
#pragma unroll
    for (int i = 0; i < 2; ++i) {
        const int m = m0 + wm * 32 + i * 16;
#pragma unroll
        for (int j = 0; j < 4; ++j) {
            const int n = n0 + wn * 32 + j * 8 + 2 * tig;
            *reinterpret_cast<float2*>(&P[(size_t)(m + g)     * H_DIM + n]) =
                make_float2(acc[i][j][0], acc[i][j][1]);
            *reinterpret_cast<float2*>(&P[(size_t)(m + g + 8) * H_DIM + n]) =
                make_float2(acc[i][j][2], acc[i][j][3]);
        }
    }
}

// -------------------------------------------------------------------------
// Squash: v = sum partials; c = v*(ns/(1+ns))/sqrt(ns+eps); also write hi/lo.
// WANT_SPLIT=0 for the final iteration (writes output only).
// -------------------------------------------------------------------------
template <int WANT_SPLIT>
__global__ __launch_bounds__(256) void squash_kernel(float* __restrict__ outp) {
    const int c = blockIdx.x;
    const int t = threadIdx.x;
    const int lane = t & 31, wid = t >> 5;

    float4 v = make_float4(0.f, 0.f, 0.f, 0.f);
#pragma unroll
    for (int z = 0; z < SPLITK; ++z) {
        float4 a = reinterpret_cast<const float4*>(g_part[z])[c * H4 + t];
        v.x += a.x; v.y += a.y; v.z += a.z; v.w += a.w;
    }

    float p = v.x * v.x + v.y * v.y + v.z * v.z + v.w * v.w;
#pragma unroll
    for (int off = 16; off; off >>= 1) p += __shfl_down_sync(0xffffffffu, p, off);

    __shared__ float wsum[8];
    if (lane == 0) wsum[wid] = p;
    __syncthreads();
    float ns = 0.f;
#pragma unroll
    for (int wq = 0; wq < 8; ++wq) ns += wsum[wq];

    const float scale = (ns / (1.0f + ns)) * rsqrtf(ns + 1e-9f);
    float4 o = make_float4(v.x * scale, v.y * scale, v.z * scale, v.w * scale);
    reinterpret_cast<float4*>(outp)[c * H4 + t] = o;

    if (WANT_SPLIT) {
        float4 h, l;
        split2(o.x, h.x, l.x); split2(o.y, h.y, l.y);
        split2(o.z, h.z, l.z); split2(o.w, h.w, l.w);
        reinterpret_cast<float4*>(g_chi)[c * H4 + t] = h;
        reinterpret_cast<float4*>(g_clo)[c * H4 + t] = l;
    }
}

// -------------------------------------------------------------------------
// Fused routing step:
//   t = sum partials (c@W) ; b += x.t ; d = softmax(b) ; s = sum_k d*x (+hi/lo)
// -------------------------------------------------------------------------
__global__ __launch_bounds__(256) void fused_route_kernel(const float* __restrict__ x) {
    const int c = blockIdx.x;
    const int t = threadIdx.x;
    const int lane = t & 31, wid = t >> 5;

    __shared__ float wsum[K_DIM][8];
    __shared__ float bsh[K_DIM];
    __shared__ float dsh[K_DIM];

    float4 tv = make_float4(0.f, 0.f, 0.f, 0.f);
#pragma unroll
    for (int z = 0; z < SPLITK; ++z) {
        float4 a = reinterpret_cast<const float4*>(g_part[z])[c * H4 + t];
        tv.x += a.x; tv.y += a.y; tv.z += a.z; tv.w += a.w;
    }

    const float4* xp = reinterpret_cast<const float4*>(x) + (size_t)c * K_DIM * H4;

#pragma unroll 4
    for (int k = 0; k < K_DIM; ++k) {
        float4 xv = __ldg(&xp[k * H4 + t]);
        float p = xv.x * tv.x + xv.y * tv.y + xv.z * tv.z + xv.w * tv.w;
#pragma unroll
        for (int off = 16; off; off >>= 1) p += __shfl_down_sync(0xffffffffu, p, off);
        if (lane == 0) wsum[k][wid] = p;
    }
    __syncthreads();

    if (t < K_DIM) {
        float bb = g_b[c * K_DIM + t];
#pragma unroll
        for (int wq = 0; wq < 8; ++wq) bb += wsum[t][wq];
        g_b[c * K_DIM + t] = bb;
        bsh[t] = bb;
    }
    __syncthreads();

    if (t < 32) {
        float b0 = bsh[t], b1 = bsh[t + 32];
        float m = fmaxf(b0, b1);
#pragma unroll
        for (int off = 16; off; off >>= 1) m = fmaxf(m, __shfl_xor_sync(0xffffffffu, m, off));
        float e0 = expf(b0 - m), e1 = expf(b1 - m);
        float ss = e0 + e1;
#pragma unroll
        for (int off = 16; off; off >>= 1) ss += __shfl_xor_sync(0xffffffffu, ss, off);
        float inv = 1.0f / ss;
        dsh[t]      = e0 * inv;
        dsh[t + 32] = e1 * inv;
    }
    __syncthreads();

    float4 acc = make_float4(0.f, 0.f, 0.f, 0.f);
#pragma unroll 4
    for (int k = 0; k < K_DIM; ++k) {
        const float dk = dsh[k];
        float4 xv = xp[k * H4 + t];
        acc.x += dk * xv.x; acc.y += dk * xv.y;
        acc.z += dk * xv.z; acc.w += dk * xv.w;
    }
    reinterpret_cast<float4*>(g_s)[c * H4 + t] = acc;

    float4 h, l;
    split2(acc.x, h.x, l.x); split2(acc.y, h.y, l.y);
    split2(acc.z, h.z, l.z); split2(acc.w, h.w, l.w);
    reinterpret_cast<float4*>(g_shi)[c * H4 + t] = h;
    reinterpret_cast<float4*>(g_slo)[c * H4 + t] = l;
}

// -------------------------------------------------------------------------
// Launch
// -------------------------------------------------------------------------
extern "C" void kernel_launch(void* const* d_in, const int* in_sizes, int n_in,
                              void* d_out, int out_size) {
    const float* x = (const float*)d_in[0];   // [512,64,1024]
    const float* W = (const float*)d_in[1];   // [1024,1024]
    float* out = (float*)d_out;               // [512,1024]

    float *shi, *slo, *chi, *clo, *whi, *wlo, *part_ptr, *c_ptr;
    cudaGetSymbolAddress((void**)&shi, g_shi);
    cudaGetSymbolAddress((void**)&slo, g_slo);
    cudaGetSymbolAddress((void**)&chi, g_chi);
    cudaGetSymbolAddress((void**)&clo, g_clo);
    cudaGetSymbolAddress((void**)&whi, g_whi);
    cudaGetSymbolAddress((void**)&wlo, g_wlo);
    cudaGetSymbolAddress((void**)&part_ptr, g_part);
    cudaGetSymbolAddress((void**)&c_ptr, g_c);

    const int smem_bytes = SMEM_FLOATS * 4;   // 82944
    static int attr_done = 0;
    cudaFuncSetAttribute(gemm_tc_kernel<1>,
                         cudaFuncAttributeMaxDynamicSharedMemorySize, smem_bytes);
    cudaFuncSetAttribute(gemm_tc_kernel<0>,
                         cudaFuncAttributeMaxDynamicSharedMemorySize, smem_bytes);
    (void)attr_done;

    const dim3 gemm_grid(H_DIM / 128, C_DIM / 64, SPLITK);  // (8, 8, 4)

    split_w_kernel<<<H_DIM, 256>>>(W);
    ws_uniform_kernel<<<C_DIM, 256>>>(x);

    for (int iter = 0; iter < 3; ++iter) {
        // c_hat = s @ W^T
        gemm_tc_kernel<1><<<gemm_grid, 256, smem_bytes>>>(shi, slo, whi, wlo, part_ptr);
        if (iter == 2)
            squash_kernel<0><<<C_DIM, 256>>>(out);
        else
            squash_kernel<1><<<C_DIM, 256>>>(c_ptr);

        if (iter < 2) {
            // t = c @ W
            gemm_tc_kernel<0><<<gemm_grid, 256, smem_bytes>>>(chi, clo, whi, wlo, part_ptr);
            fused_route_kernel<<<C_DIM, 256>>>(x);
        }
    }
}

// round 7
// speedup vs baseline: 1.2677x; 1.2677x over previous
#include <cuda_runtime.h>
#include <cuda_bf16.h>
#include <math.h>

// Problem shape (fixed): encoder_output [C,K,H] fp32, W [H,H] fp32.
#define C_DIM 512
#define K_DIM 64
#define H_DIM 1024
#define H4 (H_DIM / 4)

// GEMM: M=512, N=1024, K=1024 as 3xBF16. CTA 128x128, BK=32, split-K=4.
#define SPLITK 4
#define KSEG (H_DIM / SPLITK)   // 256
#define BK 32
#define NITER (KSEG / BK)       // 8
#define STAGES 3
#define AROW 72                 // smem row stride in bf16: 32 hi | 32 lo | 8 pad
#define STAGE_ELEMS (128 * AROW)
#define SMEM_BYTES (STAGES * 2 * STAGE_ELEMS * 2)   // 110592

// -------------------------------------------------------------------------
// Scratch (device globals only)
// -------------------------------------------------------------------------
__device__ __align__(16) __nv_bfloat16 g_shi [C_DIM * H_DIM];
__device__ __align__(16) __nv_bfloat16 g_slo [C_DIM * H_DIM];
__device__ __align__(16) __nv_bfloat16 g_chi [C_DIM * H_DIM];
__device__ __align__(16) __nv_bfloat16 g_clo [C_DIM * H_DIM];
__device__ __align__(16) __nv_bfloat16 g_wahi[H_DIM * H_DIM];  // bf16(W)      [n][k]
__device__ __align__(16) __nv_bfloat16 g_walo[H_DIM * H_DIM];
__device__ __align__(16) __nv_bfloat16 g_wbhi[H_DIM * H_DIM];  // bf16(W^T)    [n][k]
__device__ __align__(16) __nv_bfloat16 g_wblo[H_DIM * H_DIM];
__device__ __align__(16) float g_part[SPLITK][C_DIM * H_DIM];
__device__ __align__(16) float g_b   [C_DIM * K_DIM];

// -------------------------------------------------------------------------
// Helpers
// -------------------------------------------------------------------------
__device__ __forceinline__ void bf16_split(float x, __nv_bfloat16& h, __nv_bfloat16& l) {
    h = __float2bfloat16(x);
    l = __float2bfloat16(x - __bfloat162float(h));
}

__device__ __forceinline__ unsigned lds_u32(const __nv_bfloat16* p) {
    return *reinterpret_cast<const unsigned*>(p);
}

__device__ __forceinline__ void mma_bf16(float c[4],
                                         unsigned a0, unsigned a1, unsigned a2, unsigned a3,
                                         unsigned b0, unsigned b1) {
    asm volatile(
        "mma.sync.aligned.m16n8k16.row.col.f32.bf16.bf16.f32 "
        "{%0,%1,%2,%3}, {%4,%5,%6,%7}, {%8,%9}, {%0,%1,%2,%3};"
        : "+f"(c[0]), "+f"(c[1]), "+f"(c[2]), "+f"(c[3])
        : "r"(a0), "r"(a1), "r"(a2), "r"(a3), "r"(b0), "r"(b1));
}

__device__ __forceinline__ void cp16(void* smem, const void* gmem) {
    unsigned s = (unsigned)__cvta_generic_to_shared(smem);
    asm volatile("cp.async.cg.shared.global [%0], [%1], 16;" :: "r"(s), "l"(gmem));
}
__device__ __forceinline__ void cp_commit() { asm volatile("cp.async.commit_group;"); }
__device__ __forceinline__ void cp_wait1()  { asm volatile("cp.async.wait_group 1;" ::: "memory"); }

// -------------------------------------------------------------------------
// W preprocessing: bf16 hi/lo planes of W (for s@W^T) and of W^T (for c@W).
// grid (32,32), block 256.
// -------------------------------------------------------------------------
__global__ __launch_bounds__(256) void split_w_kernel(const float* __restrict__ W) {
    __shared__ __nv_bfloat16 th[32][33], tl[32][33];
    const int tx = threadIdx.x & 31, ty = threadIdx.x >> 5;
    const int bx = blockIdx.x, by = blockIdx.y;

#pragma unroll
    for (int s = 0; s < 4; ++s) {
        const int r = by * 32 + ty + s * 8;
        const int c = bx * 32 + tx;
        float v = __ldg(&W[r * H_DIM + c]);
        __nv_bfloat16 h, l;
        bf16_split(v, h, l);
        g_wahi[r * H_DIM + c] = h;
        g_walo[r * H_DIM + c] = l;
        th[ty + s * 8][tx] = h;
        tl[ty + s * 8][tx] = l;
    }
    __syncthreads();
#pragma unroll
    for (int s = 0; s < 4; ++s) {
        const int r2 = bx * 32 + ty + s * 8;   // row of W^T
        const int c2 = by * 32 + tx;
        g_wbhi[r2 * H_DIM + c2] = th[tx][ty + s * 8];
        g_wblo[r2 * H_DIM + c2] = tl[tx][ty + s * 8];
    }
}

// -------------------------------------------------------------------------
// Kernel 1: iteration-1 weighted sum (uniform d=1/64) -> s hi/lo planes; b<-0.
// -------------------------------------------------------------------------
__global__ __launch_bounds__(256) void ws_uniform_kernel(const float* __restrict__ x) {
    const int c = blockIdx.x;
    const int t = threadIdx.x;
    const float4* xp = reinterpret_cast<const float4*>(x) + (size_t)c * K_DIM * H4;

    float4 acc = make_float4(0.f, 0.f, 0.f, 0.f);
#pragma unroll 8
    for (int k = 0; k < K_DIM; ++k) {
        float4 v = __ldg(&xp[k * H4 + t]);
        acc.x += v.x; acc.y += v.y; acc.z += v.z; acc.w += v.w;
    }
    const float inv = 1.0f / (float)K_DIM;
    float o[4] = {acc.x * inv, acc.y * inv, acc.z * inv, acc.w * inv};

    __nv_bfloat16 h[4], l[4];
#pragma unroll
    for (int q = 0; q < 4; ++q) bf16_split(o[q], h[q], l[q]);
    reinterpret_cast<uint2*>(g_shi)[c * H4 + t] = *reinterpret_cast<uint2*>(h);
    reinterpret_cast<uint2*>(g_slo)[c * H4 + t] = *reinterpret_cast<uint2*>(l);

    if (t < K_DIM) g_b[c * K_DIM + t] = 0.0f;
}

// -------------------------------------------------------------------------
// 3xBF16 tensor-core GEMM: out[m,n] = sum_k (Ahi+Alo)[m,k] * (Bhi+Blo)[n,k]
// A,B stored [row][k] bf16, k contiguous. CTA 128x128, 256 thr = 8 warps
// (2m x 4n, warp tile 64x32), BK=32, 3-stage cp.async, split-K=4.
// smem rows: [hi(32) | lo(32) | pad(8)] stride AROW=72 bf16 (conflict-free).
// -------------------------------------------------------------------------
__global__ __launch_bounds__(256, 1) void gemm_bf16_kernel(
        const __nv_bfloat16* __restrict__ Ahi, const __nv_bfloat16* __restrict__ Alo,
        const __nv_bfloat16* __restrict__ Bhi, const __nv_bfloat16* __restrict__ Blo,
        float* __restrict__ part_base) {
    extern __shared__ __align__(16) __nv_bfloat16 sm[];
    __nv_bfloat16* sA = sm;                           // STAGES * STAGE_ELEMS
    __nv_bfloat16* sB = sm + STAGES * STAGE_ELEMS;

    const int tid  = threadIdx.x;
    const int w    = tid >> 5, lane = tid & 31;
    const int g    = lane >> 2, tig = lane & 3;
    const int wm   = w >> 2;          // 0..1   (64 rows each)
    const int wn   = w & 3;           // 0..3   (32 cols each)
    const int m0   = blockIdx.y * 128;
    const int n0   = blockIdx.x * 128;
    const int kbeg = blockIdx.z * KSEG;

    float acc[4][4][4];
#pragma unroll
    for (int i = 0; i < 4; ++i)
#pragma unroll
        for (int j = 0; j < 4; ++j)
#pragma unroll
            for (int q = 0; q < 4; ++q) acc[i][j][q] = 0.f;

    auto issue = [&](int it, int buf) {
        const int kw = kbeg + it * BK;
        __nv_bfloat16* aS = sA + buf * STAGE_ELEMS;
        __nv_bfloat16* bS = sB + buf * STAGE_ELEMS;
        const int q = tid & 3, r0 = tid >> 2;       // q: 16B chunk (8 bf16)
#pragma unroll
        for (int rr = 0; rr < 2; ++rr) {
            const int row = r0 + rr * 64;
            const size_t goA = (size_t)(m0 + row) * H_DIM + kw + q * 8;
            cp16(&aS[row * AROW + q * 8],      Ahi + goA);
            cp16(&aS[row * AROW + 32 + q * 8], Alo + goA);
            const size_t goB = (size_t)(n0 + row) * H_DIM + kw + q * 8;
            cp16(&bS[row * AROW + q * 8],      Bhi + goB);
            cp16(&bS[row * AROW + 32 + q * 8], Blo + goB);
        }
        cp_commit();
    };

    issue(0, 0);
    issue(1, 1);
    for (int it = 0; it < NITER; ++it) {
        const int buf = it % STAGES;
        cp_wait1();
        __syncthreads();
        if (it + 2 < NITER) issue(it + 2, (it + 2) % STAGES);
        else                cp_commit();   // empty group: keeps wait_group 1 honest

        const __nv_bfloat16* aS = sA + buf * STAGE_ELEMS;
        const __nv_bfloat16* bS = sB + buf * STAGE_ELEMS;
#pragma unroll
        for (int ks = 0; ks < BK; ks += 16) {
            unsigned ahi[4][4], alo[4][4];
#pragma unroll
            for (int i = 0; i < 4; ++i) {
                const int m = wm * 64 + i * 16;
                const __nv_bfloat16* p0 = &aS[(m + g)     * AROW + ks + 2 * tig];
                const __nv_bfloat16* p1 = &aS[(m + g + 8) * AROW + ks + 2 * tig];
                ahi[i][0] = lds_u32(p0);      ahi[i][1] = lds_u32(p1);
                ahi[i][2] = lds_u32(p0 + 8);  ahi[i][3] = lds_u32(p1 + 8);
                alo[i][0] = lds_u32(p0 + 32); alo[i][1] = lds_u32(p1 + 32);
                alo[i][2] = lds_u32(p0 + 40); alo[i][3] = lds_u32(p1 + 40);
            }
#pragma unroll
            for (int j = 0; j < 4; ++j) {
                const int n = wn * 32 + j * 8;
                const __nv_bfloat16* pb = &bS[(n + g) * AROW + ks + 2 * tig];
                unsigned bh0 = lds_u32(pb);      unsigned bh1 = lds_u32(pb + 8);
                unsigned bl0 = lds_u32(pb + 32); unsigned bl1 = lds_u32(pb + 40);
#pragma unroll
                for (int i = 0; i < 4; ++i) {
                    mma_bf16(acc[i][j], ahi[i][0], ahi[i][1], ahi[i][2], ahi[i][3], bh0, bh1);
                    mma_bf16(acc[i][j], ahi[i][0], ahi[i][1], ahi[i][2], ahi[i][3], bl0, bl1);
                    mma_bf16(acc[i][j], alo[i][0], alo[i][1], alo[i][2], alo[i][3], bh0, bh1);
                }
            }
        }
    }

    float* P = part_base + (size_t)blockIdx.z * (C_DIM * H_DIM);
#pragma unroll
    for (int i = 0; i < 4; ++i) {
        const int m = m0 + wm * 64 + i * 16;
#pragma unroll
        for (int j = 0; j < 4; ++j) {
            const int n = n0 + wn * 32 + j * 8 + 2 * tig;
            *reinterpret_cast<float2*>(&P[(size_t)(m + g)     * H_DIM + n]) =
                make_float2(acc[i][j][0], acc[i][j][1]);
            *reinterpret_cast<float2*>(&P[(size_t)(m + g + 8) * H_DIM + n]) =
                make_float2(acc[i][j][2], acc[i][j][3]);
        }
    }
}

// -------------------------------------------------------------------------
// Squash: v = sum partials; out = v*(ns/(1+ns))/sqrt(ns+eps).
// WANT_SPLIT=1 also emits bf16 hi/lo planes of c for the next GEMM.
// -------------------------------------------------------------------------
template <int WANT_SPLIT>
__global__ __launch_bounds__(256) void squash_kernel(float* __restrict__ outp) {
    const int c = blockIdx.x;
    const int t = threadIdx.x;
    const int lane = t & 31, wid = t >> 5;

    float4 v = make_float4(0.f, 0.f, 0.f, 0.f);
#pragma unroll
    for (int z = 0; z < SPLITK; ++z) {
        float4 a = reinterpret_cast<const float4*>(g_part[z])[c * H4 + t];
        v.x += a.x; v.y += a.y; v.z += a.z; v.w += a.w;
    }

    float p = v.x * v.x + v.y * v.y + v.z * v.z + v.w * v.w;
#pragma unroll
    for (int off = 16; off; off >>= 1) p += __shfl_down_sync(0xffffffffu, p, off);

    __shared__ float wsum[8];
    if (lane == 0) wsum[wid] = p;
    __syncthreads();
    float ns = 0.f;
#pragma unroll
    for (int wq = 0; wq < 8; ++wq) ns += wsum[wq];

    const float scale = (ns / (1.0f + ns)) * rsqrtf(ns + 1e-9f);
    float o[4] = {v.x * scale, v.y * scale, v.z * scale, v.w * scale};
    reinterpret_cast<float4*>(outp)[c * H4 + t] = make_float4(o[0], o[1], o[2], o[3]);

    if (WANT_SPLIT) {
        __nv_bfloat16 h[4], l[4];
#pragma unroll
        for (int q = 0; q < 4; ++q) bf16_split(o[q], h[q], l[q]);
        reinterpret_cast<uint2*>(g_chi)[c * H4 + t] = *reinterpret_cast<uint2*>(h);
        reinterpret_cast<uint2*>(g_clo)[c * H4 + t] = *reinterpret_cast<uint2*>(l);
    }
}

// -------------------------------------------------------------------------
// Fused routing step:
//   t = sum partials (c@W) ; b += x.t ; d = softmax(b) ;
//   s = sum_k d*x  -> bf16 hi/lo planes
// -------------------------------------------------------------------------
__global__ __launch_bounds__(256) void fused_route_kernel(const float* __restrict__ x) {
    const int c = blockIdx.x;
    const int t = threadIdx.x;
    const int lane = t & 31, wid = t >> 5;

    __shared__ float wsum[K_DIM][8];
    __shared__ float bsh[K_DIM];
    __shared__ float dsh[K_DIM];

    float4 tv = make_float4(0.f, 0.f, 0.f, 0.f);
#pragma unroll
    for (int z = 0; z < SPLITK; ++z) {
        float4 a = reinterpret_cast<const float4*>(g_part[z])[c * H4 + t];
        tv.x += a.x; tv.y += a.y; tv.z += a.z; tv.w += a.w;
    }

    const float4* xp = reinterpret_cast<const float4*>(x) + (size_t)c * K_DIM * H4;

#pragma unroll 4
    for (int k = 0; k < K_DIM; ++k) {
        float4 xv = __ldg(&xp[k * H4 + t]);
        float p = xv.x * tv.x + xv.y * tv.y + xv.z * tv.z + xv.w * tv.w;
#pragma unroll
        for (int off = 16; off; off >>= 1) p += __shfl_down_sync(0xffffffffu, p, off);
        if (lane == 0) wsum[k][wid] = p;
    }
    __syncthreads();

    if (t < K_DIM) {
        float bb = g_b[c * K_DIM + t];
#pragma unroll
        for (int wq = 0; wq < 8; ++wq) bb += wsum[t][wq];
        g_b[c * K_DIM + t] = bb;
        bsh[t] = bb;
    }
    __syncthreads();

    if (t < 32) {
        float b0 = bsh[t], b1 = bsh[t + 32];
        float m = fmaxf(b0, b1);
#pragma unroll
        for (int off = 16; off; off >>= 1) m = fmaxf(m, __shfl_xor_sync(0xffffffffu, m, off));
        float e0 = expf(b0 - m), e1 = expf(b1 - m);
        float ss = e0 + e1;
#pragma unroll
        for (int off = 16; off; off >>= 1) ss += __shfl_xor_sync(0xffffffffu, ss, off);
        float inv = 1.0f / ss;
        dsh[t]      = e0 * inv;
        dsh[t + 32] = e1 * inv;
    }
    __syncthreads();

    float4 acc = make_float4(0.f, 0.f, 0.f, 0.f);
#pragma unroll 4
    for (int k = 0; k < K_DIM; ++k) {
        const float dk = dsh[k];
        float4 xv = xp[k * H4 + t];
        acc.x += dk * xv.x; acc.y += dk * xv.y;
        acc.z += dk * xv.z; acc.w += dk * xv.w;
    }
    float o[4] = {acc.x, acc.y, acc.z, acc.w};
    __nv_bfloat16 h[4], l[4];
#pragma unroll
    for (int q = 0; q < 4; ++q) bf16_split(o[q], h[q], l[q]);
    reinterpret_cast<uint2*>(g_shi)[c * H4 + t] = *reinterpret_cast<uint2*>(h);
    reinterpret_cast<uint2*>(g_slo)[c * H4 + t] = *reinterpret_cast<uint2*>(l);
}

// -------------------------------------------------------------------------
// Launch
// -------------------------------------------------------------------------
extern "C" void kernel_launch(void* const* d_in, const int* in_sizes, int n_in,
                              void* d_out, int out_size) {
    const float* x = (const float*)d_in[0];   // [512,64,1024]
    const float* W = (const float*)d_in[1];   // [1024,1024]
    float* out = (float*)d_out;               // [512,1024]

    __nv_bfloat16 *shi, *slo, *chi, *clo, *wahi, *walo, *wbhi, *wblo;
    float *part_ptr;
    cudaGetSymbolAddress((void**)&shi,  g_shi);
    cudaGetSymbolAddress((void**)&slo,  g_slo);
    cudaGetSymbolAddress((void**)&chi,  g_chi);
    cudaGetSymbolAddress((void**)&clo,  g_clo);
    cudaGetSymbolAddress((void**)&wahi, g_wahi);
    cudaGetSymbolAddress((void**)&walo, g_walo);
    cudaGetSymbolAddress((void**)&wbhi, g_wbhi);
    cudaGetSymbolAddress((void**)&wblo, g_wblo);
    cudaGetSymbolAddress((void**)&part_ptr, g_part);

    cudaFuncSetAttribute(gemm_bf16_kernel,
                         cudaFuncAttributeMaxDynamicSharedMemorySize, SMEM_BYTES);

    const dim3 gemm_grid(H_DIM / 128, C_DIM / 128, SPLITK);  // (8, 4, 4) = 128

    split_w_kernel<<<dim3(32, 32), 256>>>(W);
    ws_uniform_kernel<<<C_DIM, 256>>>(x);

    for (int iter = 0; iter < 3; ++iter) {
        // c_hat = s @ W^T   (B = bf16(W) rows [n][k])
        gemm_bf16_kernel<<<gemm_grid, 256, SMEM_BYTES>>>(shi, slo, wahi, walo, part_ptr);
        if (iter == 2)
            squash_kernel<0><<<C_DIM, 256>>>(out);
        else
            squash_kernel<1><<<C_DIM, 256>>>(out);   // out unused as c-store; see below

        if (iter < 2) {
            // t = c @ W   (B = bf16(W^T) rows [n][k])
            gemm_bf16_kernel<<<gemm_grid, 256, SMEM_BYTES>>>(chi, clo, wbhi, wblo, part_ptr);
            fused_route_kernel<<<C_DIM, 256>>>(x);
        }
    }
}

// round 9
// speedup vs baseline: 1.3283x; 1.0478x over previous
#include <cuda_runtime.h>
#include <cuda_bf16.h>
#include <math.h>

// Problem shape (fixed): encoder_output [C,K,H] fp32, W [H,H] fp32.
#define C_DIM 512
#define K_DIM 64
#define H_DIM 1024
#define H4 (H_DIM / 4)

// GEMM: M=512, N=1024, K=1024 as 3xBF16. CTA 128x128, BK=32, split-K=4.
#define SPLITK 4
#define KSEG (H_DIM / SPLITK)   // 256
#define BK 32
#define NITER (KSEG / BK)       // 8
#define STAGES 3
#define AROW 72                 // smem row stride in bf16: 32 hi | 32 lo | 8 pad
#define STAGE_ELEMS (128 * AROW)
#define SMEM_BYTES (STAGES * 2 * STAGE_ELEMS * 2)   // 110592

// -------------------------------------------------------------------------
// Scratch (device globals only)
// -------------------------------------------------------------------------
__device__ __align__(16) __nv_bfloat16 g_shi [C_DIM * H_DIM];
__device__ __align__(16) __nv_bfloat16 g_slo [C_DIM * H_DIM];
__device__ __align__(16) __nv_bfloat16 g_chi [C_DIM * H_DIM];
__device__ __align__(16) __nv_bfloat16 g_clo [C_DIM * H_DIM];
__device__ __align__(16) __nv_bfloat16 g_wahi[H_DIM * H_DIM];  // bf16(W)   [n][k]
__device__ __align__(16) __nv_bfloat16 g_walo[H_DIM * H_DIM];
__device__ __align__(16) __nv_bfloat16 g_wbhi[H_DIM * H_DIM];  // bf16(W^T) [n][k]
__device__ __align__(16) __nv_bfloat16 g_wblo[H_DIM * H_DIM];
__device__ __align__(16) float g_part[SPLITK][C_DIM * H_DIM];
__device__ __align__(16) float g_b   [C_DIM * K_DIM];
__device__ __align__(16) float g_c   [C_DIM * H_DIM];   // intermediate c (fp32)

// -------------------------------------------------------------------------
// Helpers
// -------------------------------------------------------------------------
__device__ __forceinline__ void bf16_split(float x, __nv_bfloat16& h, __nv_bfloat16& l) {
    h = __float2bfloat16(x);
    l = __float2bfloat16(x - __bfloat162float(h));
}

__device__ __forceinline__ void mma_bf16(float c[4],
                                         unsigned a0, unsigned a1, unsigned a2, unsigned a3,
                                         unsigned b0, unsigned b1) {
    asm volatile(
        "mma.sync.aligned.m16n8k16.row.col.f32.bf16.bf16.f32 "
        "{%0,%1,%2,%3}, {%4,%5,%6,%7}, {%8,%9}, {%0,%1,%2,%3};"
        : "+f"(c[0]), "+f"(c[1]), "+f"(c[2]), "+f"(c[3])
        : "r"(a0), "r"(a1), "r"(a2), "r"(a3), "r"(b0), "r"(b1));
}

__device__ __forceinline__ void ldsm_x4(unsigned& r0, unsigned& r1,
                                        unsigned& r2, unsigned& r3, unsigned addr) {
    asm volatile("ldmatrix.sync.aligned.m8n8.x4.shared.b16 {%0,%1,%2,%3}, [%4];"
                 : "=r"(r0), "=r"(r1), "=r"(r2), "=r"(r3) : "r"(addr));
}

__device__ __forceinline__ void cp16(void* smem, const void* gmem) {
    unsigned s = (unsigned)__cvta_generic_to_shared(smem);
    asm volatile("cp.async.cg.shared.global [%0], [%1], 16;" :: "r"(s), "l"(gmem));
}
__device__ __forceinline__ void cp_commit() { asm volatile("cp.async.commit_group;"); }
__device__ __forceinline__ void cp_wait1()  { asm volatile("cp.async.wait_group 1;" ::: "memory"); }

// -------------------------------------------------------------------------
// W preprocessing: bf16 hi/lo planes of W (for s@W^T) and of W^T (for c@W).
// -------------------------------------------------------------------------
__global__ __launch_bounds__(256) void split_w_kernel(const float* __restrict__ W) {
    __shared__ __nv_bfloat16 th[32][33], tl[32][33];
    const int tx = threadIdx.x & 31, ty = threadIdx.x >> 5;
    const int bx = blockIdx.x, by = blockIdx.y;

#pragma unroll
    for (int s = 0; s < 4; ++s) {
        const int r = by * 32 + ty + s * 8;
        const int c = bx * 32 + tx;
        float v = __ldg(&W[r * H_DIM + c]);
        __nv_bfloat16 h, l;
        bf16_split(v, h, l);
        g_wahi[r * H_DIM + c] = h;
        g_walo[r * H_DIM + c] = l;
        th[ty + s * 8][tx] = h;
        tl[ty + s * 8][tx] = l;
    }
    __syncthreads();
#pragma unroll
    for (int s = 0; s < 4; ++s) {
        const int r2 = bx * 32 + ty + s * 8;   // row of W^T
        const int c2 = by * 32 + tx;
        g_wbhi[r2 * H_DIM + c2] = th[tx][ty + s * 8];
        g_wblo[r2 * H_DIM + c2] = tl[tx][ty + s * 8];
    }
}

// -------------------------------------------------------------------------
// Kernel 1: iteration-1 weighted sum (uniform d=1/64) -> s hi/lo planes; b<-0.
// -------------------------------------------------------------------------
__global__ __launch_bounds__(256) void ws_uniform_kernel(const float* __restrict__ x) {
    const int c = blockIdx.x;
    const int t = threadIdx.x;
    const float4* xp = reinterpret_cast<const float4*>(x) + (size_t)c * K_DIM * H4;

    float4 acc = make_float4(0.f, 0.f, 0.f, 0.f);
#pragma unroll 8
    for (int k = 0; k < K_DIM; ++k) {
        float4 v = __ldg(&xp[k * H4 + t]);
        acc.x += v.x; acc.y += v.y; acc.z += v.z; acc.w += v.w;
    }
    const float inv = 1.0f / (float)K_DIM;
    float o[4] = {acc.x * inv, acc.y * inv, acc.z * inv, acc.w * inv};

    __nv_bfloat16 h[4], l[4];
#pragma unroll
    for (int q = 0; q < 4; ++q) bf16_split(o[q], h[q], l[q]);
    reinterpret_cast<uint2*>(g_shi)[c * H4 + t] = *reinterpret_cast<uint2*>(h);
    reinterpret_cast<uint2*>(g_slo)[c * H4 + t] = *reinterpret_cast<uint2*>(l);

    if (t < K_DIM) g_b[c * K_DIM + t] = 0.0f;
}

// -------------------------------------------------------------------------
// 3xBF16 tensor-core GEMM with ldmatrix fragment loads.
//   out[m,n] = sum_k (Ahi+Alo)[m,k] * (Bhi+Blo)[n,k]
// CTA 128x128, 256 thr = 8 warps (2m x 4n, warp tile 64x32), BK=32,
// 3-stage cp.async, split-K over blockIdx.z.
// smem rows: [hi(32) | lo(32) | pad(8)] stride AROW=72 bf16 (conflict-free:
// 36 words == 4 mod 32, 8 rows x 16B cover all banks exactly once).
// -------------------------------------------------------------------------
__global__ __launch_bounds__(256, 1) void gemm_bf16_kernel(
        const __nv_bfloat16* __restrict__ Ahi, const __nv_bfloat16* __restrict__ Alo,
        const __nv_bfloat16* __restrict__ Bhi, const __nv_bfloat16* __restrict__ Blo,
        float* __restrict__ part_base) {
    extern __shared__ __align__(16) __nv_bfloat16 sm[];
    __nv_bfloat16* sA = sm;                           // STAGES * STAGE_ELEMS
    __nv_bfloat16* sB = sm + STAGES * STAGE_ELEMS;

    const int tid  = threadIdx.x;
    const int w    = tid >> 5, lane = tid & 31;
    const int g    = lane >> 2, tig = lane & 3;
    const int wm   = w >> 2;          // 0..1  (64 rows)
    const int wn   = w & 3;           // 0..3  (32 cols)
    const int m0   = blockIdx.y * 128;
    const int n0   = blockIdx.x * 128;
    const int kbeg = blockIdx.z * KSEG;

    // ldmatrix per-lane base addresses (bytes, shared space)
    const unsigned sA_base = (unsigned)__cvta_generic_to_shared(sA);
    const unsigned sB_base = (unsigned)__cvta_generic_to_shared(sB);
    // A: mats = {rows 0-7 k0, rows 8-15 k0, rows 0-7 k8, rows 8-15 k8}
    const int a_row  = lane & 15;            // lanes 0-15 rows, 16-31 repeat
    const int a_koff = (lane >> 4) << 3;     // 0 or 8
    unsigned a_addr[4];
#pragma unroll
    for (int i = 0; i < 4; ++i)
        a_addr[i] = sA_base +
            2u * ((wm * 64 + i * 16 + a_row) * AROW + a_koff);
    // B: mats = {rows 0-7 k0, rows 0-7 k8, rows 8-15 k0, rows 8-15 k8}
    const int b_row  = (lane & 7) | ((lane & 16) >> 1);
    const int b_koff = (lane & 8);           // 0 or 8
    unsigned b_addr[2];
#pragma unroll
    for (int jp = 0; jp < 2; ++jp)
        b_addr[jp] = sB_base +
            2u * ((wn * 32 + jp * 16 + b_row) * AROW + b_koff);

    float acc[4][4][4];
#pragma unroll
    for (int i = 0; i < 4; ++i)
#pragma unroll
        for (int j = 0; j < 4; ++j)
#pragma unroll
            for (int q = 0; q < 4; ++q) acc[i][j][q] = 0.f;

    auto issue = [&](int it, int buf) {
        const int kw = kbeg + it * BK;
        __nv_bfloat16* aS = sA + buf * STAGE_ELEMS;
        __nv_bfloat16* bS = sB + buf * STAGE_ELEMS;
        const int q = tid & 3, r0 = tid >> 2;       // q: 16B chunk (8 bf16)
#pragma unroll
        for (int rr = 0; rr < 2; ++rr) {
            const int row = r0 + rr * 64;
            const size_t goA = (size_t)(m0 + row) * H_DIM + kw + q * 8;
            cp16(&aS[row * AROW + q * 8],      Ahi + goA);
            cp16(&aS[row * AROW + 32 + q * 8], Alo + goA);
            const size_t goB = (size_t)(n0 + row) * H_DIM + kw + q * 8;
            cp16(&bS[row * AROW + q * 8],      Bhi + goB);
            cp16(&bS[row * AROW + 32 + q * 8], Blo + goB);
        }
        cp_commit();
    };

    issue(0, 0);
    issue(1, 1);
    for (int it = 0; it < NITER; ++it) {
        const int buf = it % STAGES;
        cp_wait1();
        __syncthreads();
        if (it + 2 < NITER) issue(it + 2, (it + 2) % STAGES);
        else                cp_commit();   // empty group keeps wait_group 1 honest

        const unsigned stage_off = (unsigned)(buf * STAGE_ELEMS * 2);
#pragma unroll
        for (int ks = 0; ks < BK; ks += 16) {
            const unsigned ks_off = stage_off + 2u * ks;
            unsigned ahi[4][4], alo[4][4];
#pragma unroll
            for (int i = 0; i < 4; ++i) {
                ldsm_x4(ahi[i][0], ahi[i][1], ahi[i][2], ahi[i][3],
                        a_addr[i] + ks_off);             // hi plane
                ldsm_x4(alo[i][0], alo[i][1], alo[i][2], alo[i][3],
                        a_addr[i] + ks_off + 64u);       // lo plane (+32 elems)
            }
#pragma unroll
            for (int jp = 0; jp < 2; ++jp) {
                unsigned bh[4], bl[4];
                ldsm_x4(bh[0], bh[1], bh[2], bh[3], b_addr[jp] + ks_off);
                ldsm_x4(bl[0], bl[1], bl[2], bl[3], b_addr[jp] + ks_off + 64u);
                const int j0 = jp * 2, j1 = jp * 2 + 1;
#pragma unroll
                for (int i = 0; i < 4; ++i) {
                    mma_bf16(acc[i][j0], ahi[i][0], ahi[i][1], ahi[i][2], ahi[i][3], bh[0], bh[1]);
                    mma_bf16(acc[i][j0], ahi[i][0], ahi[i][1], ahi[i][2], ahi[i][3], bl[0], bl[1]);
                    mma_bf16(acc[i][j0], alo[i][0], alo[i][1], alo[i][2], alo[i][3], bh[0], bh[1]);
                    mma_bf16(acc[i][j1], ahi[i][0], ahi[i][1], ahi[i][2], ahi[i][3], bh[2], bh[3]);
                    mma_bf16(acc[i][j1], ahi[i][0], ahi[i][1], ahi[i][2], ahi[i][3], bl[2], bl[3]);
                    mma_bf16(acc[i][j1], alo[i][0], alo[i][1], alo[i][2], alo[i][3], bh[2], bh[3]);
                }
            }
        }
    }

    float* P = part_base + (size_t)blockIdx.z * (C_DIM * H_DIM);
#pragma unroll
    for (int i = 0; i < 4; ++i) {
        const int m = m0 + wm * 64 + i * 16;
#pragma unroll
        for (int j = 0; j < 4; ++j) {
            const int n = n0 + wn * 32 + j * 8 + 2 * tig;
            *reinterpret_cast<float2*>(&P[(size_t)(m + g)     * H_DIM + n]) =
                make_float2(acc[i][j][0], acc[i][j][1]);
            *reinterpret_cast<float2*>(&P[(size_t)(m + g + 8) * H_DIM + n]) =
                make_float2(acc[i][j][2], acc[i][j][3]);
        }
    }
}

// -------------------------------------------------------------------------
// Squash: v = sum partials; out = v*(ns/(1+ns))/sqrt(ns+eps).
// WANT_SPLIT=1 also emits bf16 hi/lo planes of c for the next GEMM.
// -------------------------------------------------------------------------
template <int WANT_SPLIT>
__global__ __launch_bounds__(256) void squash_kernel(float* __restrict__ outp) {
    const int c = blockIdx.x;
    const int t = threadIdx.x;
    const int lane = t & 31, wid = t >> 5;

    float4 v = make_float4(0.f, 0.f, 0.f, 0.f);
#pragma unroll
    for (int z = 0; z < SPLITK; ++z) {
        float4 a = reinterpret_cast<const float4*>(g_part[z])[c * H4 + t];
        v.x += a.x; v.y += a.y; v.z += a.z; v.w += a.w;
    }

    float p = v.x * v.x + v.y * v.y + v.z * v.z + v.w * v.w;
#pragma unroll
    for (int off = 16; off; off >>= 1) p += __shfl_down_sync(0xffffffffu, p, off);

    __shared__ float wsum[8];
    if (lane == 0) wsum[wid] = p;
    __syncthreads();
    float ns = 0.f;
#pragma unroll
    for (int wq = 0; wq < 8; ++wq) ns += wsum[wq];

    const float scale = (ns / (1.0f + ns)) * rsqrtf(ns + 1e-9f);
    float o[4] = {v.x * scale, v.y * scale, v.z * scale, v.w * scale};
    reinterpret_cast<float4*>(outp)[c * H4 + t] = make_float4(o[0], o[1], o[2], o[3]);

    if (WANT_SPLIT) {
        __nv_bfloat16 h[4], l[4];
#pragma unroll
        for (int q = 0; q < 4; ++q) bf16_split(o[q], h[q], l[q]);
        reinterpret_cast<uint2*>(g_chi)[c * H4 + t] = *reinterpret_cast<uint2*>(h);
        reinterpret_cast<uint2*>(g_clo)[c * H4 + t] = *reinterpret_cast<uint2*>(l);
    }
}

// -------------------------------------------------------------------------
// Fused routing step:
//   t = sum partials (c@W) ; b += x.t ; d = softmax(b) ;
//   s = sum_k d*x  -> bf16 hi/lo planes
// -------------------------------------------------------------------------
__global__ __launch_bounds__(256) void fused_route_kernel(const float* __restrict__ x) {
    const int c = blockIdx.x;
    const int t = threadIdx.x;
    const int lane = t & 31, wid = t >> 5;

    __shared__ float wsum[K_DIM][8];
    __shared__ float bsh[K_DIM];
    __shared__ float dsh[K_DIM];

    float4 tv = make_float4(0.f, 0.f, 0.f, 0.f);
#pragma unroll
    for (int z = 0; z < SPLITK; ++z) {
        float4 a = reinterpret_cast<const float4*>(g_part[z])[c * H4 + t];
        tv.x += a.x; tv.y += a.y; tv.z += a.z; tv.w += a.w;
    }

    const float4* xp = reinterpret_cast<const float4*>(x) + (size_t)c * K_DIM * H4;

#pragma unroll 4
    for (int k = 0; k < K_DIM; ++k) {
        float4 xv = __ldg(&xp[k * H4 + t]);
        float p = xv.x * tv.x + xv.y * tv.y + xv.z * tv.z + xv.w * tv.w;
#pragma unroll
        for (int off = 16; off; off >>= 1) p += __shfl_down_sync(0xffffffffu, p, off);
        if (lane == 0) wsum[k][wid] = p;
    }
    __syncthreads();

    if (t < K_DIM) {
        float bb = g_b[c * K_DIM + t];
#pragma unroll
        for (int wq = 0; wq < 8; ++wq) bb += wsum[t][wq];
        g_b[c * K_DIM + t] = bb;
        bsh[t] = bb;
    }
    __syncthreads();

    if (t < 32) {
        float b0 = bsh[t], b1 = bsh[t + 32];
        float m = fmaxf(b0, b1);
#pragma unroll
        for (int off = 16; off; off >>= 1) m = fmaxf(m, __shfl_xor_sync(0xffffffffu, m, off));
        float e0 = expf(b0 - m), e1 = expf(b1 - m);
        float ss = e0 + e1;
#pragma unroll
        for (int off = 16; off; off >>= 1) ss += __shfl_xor_sync(0xffffffffu, ss, off);
        float inv = 1.0f / ss;
        dsh[t]      = e0 * inv;
        dsh[t + 32] = e1 * inv;
    }
    __syncthreads();

    float4 acc = make_float4(0.f, 0.f, 0.f, 0.f);
#pragma unroll 4
    for (int k = 0; k < K_DIM; ++k) {
        const float dk = dsh[k];
        float4 xv = xp[k * H4 + t];
        acc.x += dk * xv.x; acc.y += dk * xv.y;
        acc.z += dk * xv.z; acc.w += dk * xv.w;
    }
    float o[4] = {acc.x, acc.y, acc.z, acc.w};
    __nv_bfloat16 h[4], l[4];
#pragma unroll
    for (int q = 0; q < 4; ++q) bf16_split(o[q], h[q], l[q]);
    reinterpret_cast<uint2*>(g_shi)[c * H4 + t] = *reinterpret_cast<uint2*>(h);
    reinterpret_cast<uint2*>(g_slo)[c * H4 + t] = *reinterpret_cast<uint2*>(l);
}

// -------------------------------------------------------------------------
// Launch
// -------------------------------------------------------------------------
extern "C" void kernel_launch(void* const* d_in, const int* in_sizes, int n_in,
                              void* d_out, int out_size) {
    const float* x = (const float*)d_in[0];   // [512,64,1024]
    const float* W = (const float*)d_in[1];   // [1024,1024]
    float* out = (float*)d_out;               // [512,1024]

    __nv_bfloat16 *shi, *slo, *chi, *clo, *wahi, *walo, *wbhi, *wblo;
    float *part_ptr, *c_ptr;
    cudaGetSymbolAddress((void**)&shi,  g_shi);
    cudaGetSymbolAddress((void**)&slo,  g_slo);
    cudaGetSymbolAddress((void**)&chi,  g_chi);
    cudaGetSymbolAddress((void**)&clo,  g_clo);
    cudaGetSymbolAddress((void**)&wahi, g_wahi);
    cudaGetSymbolAddress((void**)&walo, g_walo);
    cudaGetSymbolAddress((void**)&wbhi, g_wbhi);
    cudaGetSymbolAddress((void**)&wblo, g_wblo);
    cudaGetSymbolAddress((void**)&part_ptr, g_part);
    cudaGetSymbolAddress((void**)&c_ptr, g_c);

    cudaFuncSetAttribute(gemm_bf16_kernel,
                         cudaFuncAttributeMaxDynamicSharedMemorySize, SMEM_BYTES);

    const dim3 gemm_grid(H_DIM / 128, C_DIM / 128, SPLITK);  // (8, 4, 4) = 128

    split_w_kernel<<<dim3(32, 32), 256>>>(W);
    ws_uniform_kernel<<<C_DIM, 256>>>(x);

    for (int iter = 0; iter < 3; ++iter) {
        // c_hat = s @ W^T   (B = bf16(W) rows [n][k])
        gemm_bf16_kernel<<<gemm_grid, 256, SMEM_BYTES>>>(shi, slo, wahi, walo, part_ptr);
        if (iter == 2)
            squash_kernel<0><<<C_DIM, 256>>>(out);
        else
            squash_kernel<1><<<C_DIM, 256>>>(c_ptr);

        if (iter < 2) {
            // t = c @ W   (B = bf16(W^T) rows [n][k])
            gemm_bf16_kernel<<<gemm_grid, 256, SMEM_BYTES>>>(chi, clo, wbhi, wblo, part_ptr);
            fused_route_kernel<<<C_DIM, 256>>>(x);
        }
    }
}

// round 12
// speedup vs baseline: 1.4236x; 1.0717x over previous
#include <cuda_runtime.h>
#include <cuda_bf16.h>
#include <math.h>

// Problem shape (fixed): encoder_output [C,K,H] fp32, W [H,H] fp32.
#define C_DIM 512
#define K_DIM 64
#define H_DIM 1024
#define H4 (H_DIM / 4)

// GEMM: M=512, N=1024, K=1024 as 3xBF16 mma.sync. CTA 128x128, BK=32.
// split-K=8 -> grid 256 CTAs (~2/SM), 2-stage cp.async, 2 CTAs/SM.
#define SPLITK 8
#define KSEG (H_DIM / SPLITK)   // 128
#define BK 32
#define NITER (KSEG / BK)       // 4
#define STAGES 2
#define AROW 72                 // smem row stride in bf16: 32 hi | 32 lo | 8 pad
#define STAGE_ELEMS (128 * AROW)
#define SMEM_BYTES (STAGES * 2 * STAGE_ELEMS * 2)   // 73728

// -------------------------------------------------------------------------
// Scratch (device globals only)
// -------------------------------------------------------------------------
__device__ __align__(16) __nv_bfloat16 g_shi [C_DIM * H_DIM];
__device__ __align__(16) __nv_bfloat16 g_slo [C_DIM * H_DIM];
__device__ __align__(16) __nv_bfloat16 g_chi [C_DIM * H_DIM];
__device__ __align__(16) __nv_bfloat16 g_clo [C_DIM * H_DIM];
__device__ __align__(16) __nv_bfloat16 g_wahi[H_DIM * H_DIM];  // bf16(W)   [n][k]
__device__ __align__(16) __nv_bfloat16 g_walo[H_DIM * H_DIM];
__device__ __align__(16) __nv_bfloat16 g_wbhi[H_DIM * H_DIM];  // bf16(W^T) [n][k]
__device__ __align__(16) __nv_bfloat16 g_wblo[H_DIM * H_DIM];
__device__ __align__(16) float g_part[SPLITK][C_DIM * H_DIM];
__device__ __align__(16) float g_b   [C_DIM * K_DIM];
__device__ __align__(16) float g_c   [C_DIM * H_DIM];   // intermediate c (fp32)

// -------------------------------------------------------------------------
// Helpers
// -------------------------------------------------------------------------
__device__ __forceinline__ void bf16_split(float x, __nv_bfloat16& h, __nv_bfloat16& l) {
    h = __float2bfloat16(x);
    l = __float2bfloat16(x - __bfloat162float(h));
}

__device__ __forceinline__ void mma_bf16(float c[4],
                                         unsigned a0, unsigned a1, unsigned a2, unsigned a3,
                                         unsigned b0, unsigned b1) {
    asm volatile(
        "mma.sync.aligned.m16n8k16.row.col.f32.bf16.bf16.f32 "
        "{%0,%1,%2,%3}, {%4,%5,%6,%7}, {%8,%9}, {%0,%1,%2,%3};"
        : "+f"(c[0]), "+f"(c[1]), "+f"(c[2]), "+f"(c[3])
        : "r"(a0), "r"(a1), "r"(a2), "r"(a3), "r"(b0), "r"(b1));
}

__device__ __forceinline__ void ldsm_x4(unsigned& r0, unsigned& r1,
                                        unsigned& r2, unsigned& r3, unsigned addr) {
    asm volatile("ldmatrix.sync.aligned.m8n8.x4.shared.b16 {%0,%1,%2,%3}, [%4];"
                 : "=r"(r0), "=r"(r1), "=r"(r2), "=r"(r3) : "r"(addr));
}

__device__ __forceinline__ void cp16(void* smem, const void* gmem) {
    unsigned s = (unsigned)__cvta_generic_to_shared(smem);
    asm volatile("cp.async.cg.shared.global [%0], [%1], 16;" :: "r"(s), "l"(gmem));
}
__device__ __forceinline__ void cp_commit() { asm volatile("cp.async.commit_group;"); }
__device__ __forceinline__ void cp_wait0()  { asm volatile("cp.async.wait_group 0;" ::: "memory"); }

// -------------------------------------------------------------------------
// W preprocessing: bf16 hi/lo planes of W (for s@W^T) and of W^T (for c@W).
// -------------------------------------------------------------------------
__global__ __launch_bounds__(256) void split_w_kernel(const float* __restrict__ W) {
    __shared__ __nv_bfloat16 th[32][33], tl[32][33];
    const int tx = threadIdx.x & 31, ty = threadIdx.x >> 5;
    const int bx = blockIdx.x, by = blockIdx.y;

#pragma unroll
    for (int s = 0; s < 4; ++s) {
        const int r = by * 32 + ty + s * 8;
        const int c = bx * 32 + tx;
        float v = __ldg(&W[r * H_DIM + c]);
        __nv_bfloat16 h, l;
        bf16_split(v, h, l);
        g_wahi[r * H_DIM + c] = h;
        g_walo[r * H_DIM + c] = l;
        th[ty + s * 8][tx] = h;
        tl[ty + s * 8][tx] = l;
    }
    __syncthreads();
#pragma unroll
    for (int s = 0; s < 4; ++s) {
        const int r2 = bx * 32 + ty + s * 8;   // row of W^T
        const int c2 = by * 32 + tx;
        g_wbhi[r2 * H_DIM + c2] = th[tx][ty + s * 8];
        g_wblo[r2 * H_DIM + c2] = tl[tx][ty + s * 8];
    }
}

// -------------------------------------------------------------------------
// Kernel 1: iteration-1 weighted sum (uniform d=1/64) -> s hi/lo planes; b<-0.
// -------------------------------------------------------------------------
__global__ __launch_bounds__(256) void ws_uniform_kernel(const float* __restrict__ x) {
    const int c = blockIdx.x;
    const int t = threadIdx.x;
    const float4* xp = reinterpret_cast<const float4*>(x) + (size_t)c * K_DIM * H4;

    float4 acc = make_float4(0.f, 0.f, 0.f, 0.f);
#pragma unroll 8
    for (int k = 0; k < K_DIM; ++k) {
        float4 v = __ldg(&xp[k * H4 + t]);
        acc.x += v.x; acc.y += v.y; acc.z += v.z; acc.w += v.w;
    }
    const float inv = 1.0f / (float)K_DIM;
    float o[4] = {acc.x * inv, acc.y * inv, acc.z * inv, acc.w * inv};

    __nv_bfloat16 h[4], l[4];
#pragma unroll
    for (int q = 0; q < 4; ++q) bf16_split(o[q], h[q], l[q]);
    reinterpret_cast<uint2*>(g_shi)[c * H4 + t] = *reinterpret_cast<uint2*>(h);
    reinterpret_cast<uint2*>(g_slo)[c * H4 + t] = *reinterpret_cast<uint2*>(l);

    if (t < K_DIM) g_b[c * K_DIM + t] = 0.0f;
}

// -------------------------------------------------------------------------
// 3xBF16 tensor-core GEMM with ldmatrix fragment loads.
//   out[m,n] = sum_k (Ahi+Alo)[m,k] * (Bhi+Blo)[n,k]
// CTA 128x128, 256 thr = 8 warps (2m x 4n, warp tile 64x32), BK=32,
// 2-stage cp.async double buffer, split-K over blockIdx.z, 2 CTAs/SM.
// smem rows: [hi(32) | lo(32) | pad(8)] stride AROW=72 bf16 (conflict-free).
// -------------------------------------------------------------------------
__global__ __launch_bounds__(256, 2) void gemm_bf16_kernel(
        const __nv_bfloat16* __restrict__ Ahi, const __nv_bfloat16* __restrict__ Alo,
        const __nv_bfloat16* __restrict__ Bhi, const __nv_bfloat16* __restrict__ Blo,
        float* __restrict__ part_base) {
    extern __shared__ __align__(16) __nv_bfloat16 sm[];
    __nv_bfloat16* sA = sm;                           // STAGES * STAGE_ELEMS
    __nv_bfloat16* sB = sm + STAGES * STAGE_ELEMS;

    const int tid  = threadIdx.x;
    const int w    = tid >> 5, lane = tid & 31;
    const int g    = lane >> 2, tig = lane & 3;
    const int wm   = w >> 2;          // 0..1  (64 rows)
    const int wn   = w & 3;           // 0..3  (32 cols)
    const int m0   = blockIdx.y * 128;
    const int n0   = blockIdx.x * 128;
    const int kbeg = blockIdx.z * KSEG;

    // ldmatrix per-lane base addresses (bytes, shared space)
    const unsigned sA_base = (unsigned)__cvta_generic_to_shared(sA);
    const unsigned sB_base = (unsigned)__cvta_generic_to_shared(sB);
    const int a_row  = lane & 15;
    const int a_koff = (lane >> 4) << 3;
    unsigned a_addr[4];
#pragma unroll
    for (int i = 0; i < 4; ++i)
        a_addr[i] = sA_base + 2u * ((wm * 64 + i * 16 + a_row) * AROW + a_koff);
    const int b_row  = (lane & 7) | ((lane & 16) >> 1);
    const int b_koff = (lane & 8);
    unsigned b_addr[2];
#pragma unroll
    for (int jp = 0; jp < 2; ++jp)
        b_addr[jp] = sB_base + 2u * ((wn * 32 + jp * 16 + b_row) * AROW + b_koff);

    float acc[4][4][4];
#pragma unroll
    for (int i = 0; i < 4; ++i)
#pragma unroll
        for (int j = 0; j < 4; ++j)
#pragma unroll
            for (int q = 0; q < 4; ++q) acc[i][j][q] = 0.f;

    auto issue = [&](int it, int buf) {
        const int kw = kbeg + it * BK;
        __nv_bfloat16* aS = sA + buf * STAGE_ELEMS;
        __nv_bfloat16* bS = sB + buf * STAGE_ELEMS;
        const int q = tid & 3, r0 = tid >> 2;       // q: 16B chunk (8 bf16)
#pragma unroll
        for (int rr = 0; rr < 2; ++rr) {
            const int row = r0 + rr * 64;
            const size_t goA = (size_t)(m0 + row) * H_DIM + kw + q * 8;
            cp16(&aS[row * AROW + q * 8],      Ahi + goA);
            cp16(&aS[row * AROW + 32 + q * 8], Alo + goA);
            const size_t goB = (size_t)(n0 + row) * H_DIM + kw + q * 8;
            cp16(&bS[row * AROW + q * 8],      Bhi + goB);
            cp16(&bS[row * AROW + 32 + q * 8], Blo + goB);
        }
        cp_commit();
    };

    issue(0, 0);
    for (int it = 0; it < NITER; ++it) {
        const int buf = it & 1;
        cp_wait0();
        __syncthreads();
        if (it + 1 < NITER) issue(it + 1, buf ^ 1);

        const unsigned stage_off = (unsigned)(buf * STAGE_ELEMS * 2);
#pragma unroll
        for (int ks = 0; ks < BK; ks += 16) {
            const unsigned ks_off = stage_off + 2u * ks;
            unsigned ahi[4][4], alo[4][4];
#pragma unroll
            for (int i = 0; i < 4; ++i) {
                ldsm_x4(ahi[i][0], ahi[i][1], ahi[i][2], ahi[i][3],
                        a_addr[i] + ks_off);             // hi plane
                ldsm_x4(alo[i][0], alo[i][1], alo[i][2], alo[i][3],
                        a_addr[i] + ks_off + 64u);       // lo plane (+32 elems)
            }
#pragma unroll
            for (int jp = 0; jp < 2; ++jp) {
                unsigned bh[4], bl[4];
                ldsm_x4(bh[0], bh[1], bh[2], bh[3], b_addr[jp] + ks_off);
                ldsm_x4(bl[0], bl[1], bl[2], bl[3], b_addr[jp] + ks_off + 64u);
                const int j0 = jp * 2, j1 = jp * 2 + 1;
#pragma unroll
                for (int i = 0; i < 4; ++i) {
                    mma_bf16(acc[i][j0], ahi[i][0], ahi[i][1], ahi[i][2], ahi[i][3], bh[0], bh[1]);
                    mma_bf16(acc[i][j0], ahi[i][0], ahi[i][1], ahi[i][2], ahi[i][3], bl[0], bl[1]);
                    mma_bf16(acc[i][j0], alo[i][0], alo[i][1], alo[i][2], alo[i][3], bh[0], bh[1]);
                    mma_bf16(acc[i][j1], ahi[i][0], ahi[i][1], ahi[i][2], ahi[i][3], bh[2], bh[3]);
                    mma_bf16(acc[i][j1], ahi[i][0], ahi[i][1], ahi[i][2], ahi[i][3], bl[2], bl[3]);
                    mma_bf16(acc[i][j1], alo[i][0], alo[i][1], alo[i][2], alo[i][3], bh[2], bh[3]);
                }
            }
        }
        __syncthreads();
    }

    float* P = part_base + (size_t)blockIdx.z * (C_DIM * H_DIM);
#pragma unroll
    for (int i = 0; i < 4; ++i) {
        const int m = m0 + wm * 64 + i * 16;
#pragma unroll
        for (int j = 0; j < 4; ++j) {
            const int n = n0 + wn * 32 + j * 8 + 2 * tig;
            *reinterpret_cast<float2*>(&P[(size_t)(m + g)     * H_DIM + n]) =
                make_float2(acc[i][j][0], acc[i][j][1]);
            *reinterpret_cast<float2*>(&P[(size_t)(m + g + 8) * H_DIM + n]) =
                make_float2(acc[i][j][2], acc[i][j][3]);
        }
    }
}

// -------------------------------------------------------------------------
// Squash: v = sum partials; out = v*(ns/(1+ns))/sqrt(ns+eps).
// WANT_SPLIT=1 also emits bf16 hi/lo planes of c for the next GEMM.
// -------------------------------------------------------------------------
template <int WANT_SPLIT>
__global__ __launch_bounds__(256) void squash_kernel(float* __restrict__ outp) {
    const int c = blockIdx.x;
    const int t = threadIdx.x;
    const int lane = t & 31, wid = t >> 5;

    float4 v = make_float4(0.f, 0.f, 0.f, 0.f);
#pragma unroll
    for (int z = 0; z < SPLITK; ++z) {
        float4 a = reinterpret_cast<const float4*>(g_part[z])[c * H4 + t];
        v.x += a.x; v.y += a.y; v.z += a.z; v.w += a.w;
    }

    float p = v.x * v.x + v.y * v.y + v.z * v.z + v.w * v.w;
#pragma unroll
    for (int off = 16; off; off >>= 1) p += __shfl_down_sync(0xffffffffu, p, off);

    __shared__ float wsum[8];
    if (lane == 0) wsum[wid] = p;
    __syncthreads();
    float ns = 0.f;
#pragma unroll
    for (int wq = 0; wq < 8; ++wq) ns += wsum[wq];

    const float scale = (ns / (1.0f + ns)) * rsqrtf(ns + 1e-9f);
    float o[4] = {v.x * scale, v.y * scale, v.z * scale, v.w * scale};
    reinterpret_cast<float4*>(outp)[c * H4 + t] = make_float4(o[0], o[1], o[2], o[3]);

    if (WANT_SPLIT) {
        __nv_bfloat16 h[4], l[4];
#pragma unroll
        for (int q = 0; q < 4; ++q) bf16_split(o[q], h[q], l[q]);
        reinterpret_cast<uint2*>(g_chi)[c * H4 + t] = *reinterpret_cast<uint2*>(h);
        reinterpret_cast<uint2*>(g_clo)[c * H4 + t] = *reinterpret_cast<uint2*>(l);
    }
}

// -------------------------------------------------------------------------
// Fused routing step:
//   t = sum partials (c@W) -> smem ; b += x.t (warp-per-8k, accumulate-then-
//   reduce) ; d = softmax(b) ; s = sum_k d*x -> bf16 hi/lo planes
// -------------------------------------------------------------------------
__global__ __launch_bounds__(256) void fused_route_kernel(const float* __restrict__ x) {
    const int c = blockIdx.x;
    const int t = threadIdx.x;
    const int lane = t & 31, wid = t >> 5;

    __shared__ float4 tsh[H4];       // t vector (4 KB)
    __shared__ float bsh[K_DIM];
    __shared__ float dsh[K_DIM];

    // t = sum of split-K partials, cached in smem
    float4 tv = make_float4(0.f, 0.f, 0.f, 0.f);
#pragma unroll
    for (int z = 0; z < SPLITK; ++z) {
        float4 a = reinterpret_cast<const float4*>(g_part[z])[c * H4 + t];
        tv.x += a.x; tv.y += a.y; tv.z += a.z; tv.w += a.w;
    }
    tsh[t] = tv;
    __syncthreads();

    const float4* xp = reinterpret_cast<const float4*>(x) + (size_t)c * K_DIM * H4;

    // ---- Phase A: each warp owns 8 k's; scalar accumulate, one reduce per k
    const int k0 = wid * 8;
    float dots[8];
#pragma unroll
    for (int kk = 0; kk < 8; ++kk) {
        const float4* xr = xp + (k0 + kk) * H4;
        float d = 0.f;
#pragma unroll
        for (int j = 0; j < 8; ++j) {
            const int idx = lane + 32 * j;
            float4 xv = __ldg(&xr[idx]);
            float4 t4 = tsh[idx];
            d += xv.x * t4.x + xv.y * t4.y + xv.z * t4.z + xv.w * t4.w;
        }
        dots[kk] = d;
    }
#pragma unroll
    for (int kk = 0; kk < 8; ++kk) {
        float d = dots[kk];
#pragma unroll
        for (int off = 16; off; off >>= 1) d += __shfl_down_sync(0xffffffffu, d, off);
        if (lane == 0) bsh[k0 + kk] = d;
    }
    __syncthreads();

    if (t < K_DIM) {
        float bb = g_b[c * K_DIM + t] + bsh[t];
        g_b[c * K_DIM + t] = bb;
        bsh[t] = bb;
    }
    __syncthreads();

    // ---- Softmax over K=64 in warp 0 ----
    if (t < 32) {
        float b0 = bsh[t], b1 = bsh[t + 32];
        float m = fmaxf(b0, b1);
#pragma unroll
        for (int off = 16; off; off >>= 1) m = fmaxf(m, __shfl_xor_sync(0xffffffffu, m, off));
        float e0 = expf(b0 - m), e1 = expf(b1 - m);
        float ss = e0 + e1;
#pragma unroll
        for (int off = 16; off; off >>= 1) ss += __shfl_xor_sync(0xffffffffu, ss, off);
        float inv = 1.0f / ss;
        dsh[t]      = e0 * inv;
        dsh[t + 32] = e1 * inv;
    }
    __syncthreads();

    // ---- Phase B: weighted sum (x re-read, L2-resident) ----
    float4 acc = make_float4(0.f, 0.f, 0.f, 0.f);
#pragma unroll 4
    for (int k = 0; k < K_DIM; ++k) {
        const float dk = dsh[k];
        float4 xv = xp[k * H4 + t];
        acc.x += dk * xv.x; acc.y += dk * xv.y;
        acc.z += dk * xv.z; acc.w += dk * xv.w;
    }
    float o[4] = {acc.x, acc.y, acc.z, acc.w};
    __nv_bfloat16 h[4], l[4];
#pragma unroll
    for (int q = 0; q < 4; ++q) bf16_split(o[q], h[q], l[q]);
    reinterpret_cast<uint2*>(g_shi)[c * H4 + t] = *reinterpret_cast<uint2*>(h);
    reinterpret_cast<uint2*>(g_slo)[c * H4 + t] = *reinterpret_cast<uint2*>(l);
}

// -------------------------------------------------------------------------
// Launch
// -------------------------------------------------------------------------
extern "C" void kernel_launch(void* const* d_in, const int* in_sizes, int n_in,
                              void* d_out, int out_size) {
    const float* x = (const float*)d_in[0];   // [512,64,1024]
    const float* W = (const float*)d_in[1];   // [1024,1024]
    float* out = (float*)d_out;               // [512,1024]

    __nv_bfloat16 *shi, *slo, *chi, *clo, *wahi, *walo, *wbhi, *wblo;
    float *part_ptr, *c_ptr;
    cudaGetSymbolAddress((void**)&shi,  g_shi);
    cudaGetSymbolAddress((void**)&slo,  g_slo);
    cudaGetSymbolAddress((void**)&chi,  g_chi);
    cudaGetSymbolAddress((void**)&clo,  g_clo);
    cudaGetSymbolAddress((void**)&wahi, g_wahi);
    cudaGetSymbolAddress((void**)&walo, g_walo);
    cudaGetSymbolAddress((void**)&wbhi, g_wbhi);
    cudaGetSymbolAddress((void**)&wblo, g_wblo);
    cudaGetSymbolAddress((void**)&part_ptr, g_part);
    cudaGetSymbolAddress((void**)&c_ptr, g_c);

    cudaFuncSetAttribute(gemm_bf16_kernel,
                         cudaFuncAttributeMaxDynamicSharedMemorySize, SMEM_BYTES);

    const dim3 gemm_grid(H_DIM / 128, C_DIM / 128, SPLITK);  // (8, 4, 8) = 256

    split_w_kernel<<<dim3(32, 32), 256>>>(W);
    ws_uniform_kernel<<<C_DIM, 256>>>(x);

    for (int iter = 0; iter < 3; ++iter) {
        // c_hat = s @ W^T   (B = bf16(W) rows [n][k])
        gemm_bf16_kernel<<<gemm_grid, 256, SMEM_BYTES>>>(shi, slo, wahi, walo, part_ptr);
        if (iter == 2)
            squash_kernel<0><<<C_DIM, 256>>>(out);
        else
            squash_kernel<1><<<C_DIM, 256>>>(c_ptr);

        if (iter < 2) {
            // t = c @ W   (B = bf16(W^T) rows [n][k])
            gemm_bf16_kernel<<<gemm_grid, 256, SMEM_BYTES>>>(chi, clo, wbhi, wblo, part_ptr);
            fused_route_kernel<<<C_DIM, 256>>>(x);
        }
    }
}